// round 2
// baseline (speedup 1.0000x reference)
#include <cuda_runtime.h>
#include <math.h>

#define BB   8
#define NN   128
#define CC   256
#define HID  1024
#define EPSF 1e-5f
#define TILE 32
#define ROWS (BB*NN)          /* 1024  */
#define EDGES (BB*NN*NN)      /* 131072 */

// ---------------- scratch (device globals; no allocation anywhere) ---------
__device__ float g_x1[ROWS*CC];
__device__ float g_q [ROWS*CC];
__device__ float g_k [ROWS*CC];
__device__ float g_v [ROWS*CC];
__device__ float g_agg[ROWS*CC];
__device__ float g_attn[EDGES*CC];   // 134 MB
__device__ float g_y2 [EDGES*CC];    // 134 MB

__device__ __forceinline__ float warpSum(float v) {
#pragma unroll
    for (int o = 16; o > 0; o >>= 1) v += __shfl_xor_sync(0xffffffffu, v, o);
    return v;
}

// 256-thread block sum; all threads get the result.
__device__ __forceinline__ float blockSum(float v, float* sred, int t) {
    v = warpSum(v);
    __syncthreads();                       // protect sred from previous use
    if ((t & 31) == 0) sred[t >> 5] = v;
    __syncthreads();
    float tot = 0.f;
#pragma unroll
    for (int w = 0; w < 8; w++) tot += sred[w];
    return tot;
}

// =================== K1: LN1 + q,k,v projections (per node row) ============
__global__ void __launch_bounds__(256) k1_node_qkv(
    const float* __restrict__ x,
    const float* __restrict__ Wq, const float* __restrict__ bq,
    const float* __restrict__ Wk, const float* __restrict__ bk,
    const float* __restrict__ Wv, const float* __restrict__ bv,
    const float* __restrict__ ln1_s, const float* __restrict__ ln1_b)
{
    __shared__ __align__(16) float sx[CC];
    __shared__ float sred[8];
    int r = blockIdx.x, t = threadIdx.x;

    float xv = x[r*CC + t];
    float mean = blockSum(xv, sred, t) * (1.f/CC);
    float d = xv - mean;
    float var = blockSum(d*d, sred, t) * (1.f/CC);
    float rs = rsqrtf(var + EPSF);
    float x1 = d * rs * ln1_s[t] + ln1_b[t];
    sx[t] = x1;
    g_x1[r*CC + t] = x1;
    __syncthreads();

    float aq = bq[t], ak = bk[t], av = bv[t];
    const float4* sx4 = (const float4*)sx;
#pragma unroll 1
    for (int k4 = 0; k4 < CC/4; k4++) {
        float4 xv4 = sx4[k4];
        int kk = 4*k4;
        aq = fmaf(xv4.x, Wq[(kk+0)*CC+t], aq);
        aq = fmaf(xv4.y, Wq[(kk+1)*CC+t], aq);
        aq = fmaf(xv4.z, Wq[(kk+2)*CC+t], aq);
        aq = fmaf(xv4.w, Wq[(kk+3)*CC+t], aq);
        ak = fmaf(xv4.x, Wk[(kk+0)*CC+t], ak);
        ak = fmaf(xv4.y, Wk[(kk+1)*CC+t], ak);
        ak = fmaf(xv4.z, Wk[(kk+2)*CC+t], ak);
        ak = fmaf(xv4.w, Wk[(kk+3)*CC+t], ak);
        av = fmaf(xv4.x, Wv[(kk+0)*CC+t], av);
        av = fmaf(xv4.y, Wv[(kk+1)*CC+t], av);
        av = fmaf(xv4.z, Wv[(kk+2)*CC+t], av);
        av = fmaf(xv4.w, Wv[(kk+3)*CC+t], av);
    }
    g_q[r*CC+t] = aq;  g_k[r*CC+t] = ak;  g_v[r*CC+t] = av;
}

// =================== K2: e = y@We+be ; attn = (q*k/sqrt(dk))*(e+1)*e =======
__global__ void __launch_bounds__(256) k2_edge_attn(
    const float* __restrict__ y,
    const float* __restrict__ We, const float* __restrict__ be)
{
    __shared__ __align__(16) float ys[TILE][CC];
    int base = blockIdx.x * TILE;        // edge index base (same b,i for tile)
    int t = threadIdx.x;
    int ri = base / NN;                  // b*N + i
    int b  = ri >> 7;
    int j0 = base & (NN - 1);

#pragma unroll
    for (int r = 0; r < TILE; r++)
        ys[r][t] = y[(size_t)(base + r)*CC + t];
    __syncthreads();

    float acc[TILE];
    float bev = be[t];
#pragma unroll
    for (int r = 0; r < TILE; r++) acc[r] = bev;

#pragma unroll 1
    for (int k4 = 0; k4 < CC/4; k4++) {
        int kk = 4*k4;
        float w0 = We[(kk+0)*CC+t];
        float w1 = We[(kk+1)*CC+t];
        float w2 = We[(kk+2)*CC+t];
        float w3 = We[(kk+3)*CC+t];
#pragma unroll
        for (int r = 0; r < TILE; r++) {
            float4 yv = ((const float4*)ys[r])[k4];     // broadcast LDS.128
            acc[r] = fmaf(yv.x, w0, acc[r]);
            acc[r] = fmaf(yv.y, w1, acc[r]);
            acc[r] = fmaf(yv.z, w2, acc[r]);
            acc[r] = fmaf(yv.w, w3, acc[r]);
        }
    }

    float qv = g_q[ri*CC + t] * 0.17677669529663687f;   // 1/sqrt(32) folded
    int krow = (b << 7) + j0;
#pragma unroll
    for (int r = 0; r < TILE; r++) {
        float e  = acc[r];
        float kv = g_k[(krow + r)*CC + t];
        g_attn[(size_t)(base + r)*CC + t] = qv * kv * (e + 1.f) * e;
    }
}

// =================== K3: edge_out = attn@Woe+boe ; y2 = LN4(edge_out + y) ==
__global__ void __launch_bounds__(256) k3_edgeout_ln(
    const float* __restrict__ y,
    const float* __restrict__ Woe, const float* __restrict__ boe,
    const float* __restrict__ ln4_s, const float* __restrict__ ln4_b)
{
    __shared__ __align__(16) float as[TILE][CC];
    int base = blockIdx.x * TILE;
    int t = threadIdx.x;

#pragma unroll
    for (int r = 0; r < TILE; r++)
        as[r][t] = g_attn[(size_t)(base + r)*CC + t];
    __syncthreads();

    float acc[TILE];
    float bv = boe[t];
#pragma unroll
    for (int r = 0; r < TILE; r++) acc[r] = bv;

#pragma unroll 1
    for (int k4 = 0; k4 < CC/4; k4++) {
        int kk = 4*k4;
        float w0 = Woe[(kk+0)*CC+t];
        float w1 = Woe[(kk+1)*CC+t];
        float w2 = Woe[(kk+2)*CC+t];
        float w3 = Woe[(kk+3)*CC+t];
#pragma unroll
        for (int r = 0; r < TILE; r++) {
            float4 yv = ((const float4*)as[r])[k4];
            acc[r] = fmaf(yv.x, w0, acc[r]);
            acc[r] = fmaf(yv.y, w1, acc[r]);
            acc[r] = fmaf(yv.z, w2, acc[r]);
            acc[r] = fmaf(yv.w, w3, acc[r]);
        }
    }
    __syncthreads();
#pragma unroll
    for (int r = 0; r < TILE; r++)
        as[r][t] = acc[r] + y[(size_t)(base + r)*CC + t];
    __syncthreads();

    // LN4 per row, one warp per row (8 warps x 4 rounds)
    int w = t >> 5, l = t & 31;
#pragma unroll
    for (int u = 0; u < 4; u++) {
        int r = (u << 3) + w;
        float s = 0.f, sq = 0.f;
#pragma unroll
        for (int c0 = 0; c0 < CC; c0 += 32) {
            float v = as[r][c0 + l];
            s += v; sq = fmaf(v, v, sq);
        }
        s = warpSum(s); sq = warpSum(sq);
        float m  = s * (1.f/CC);
        float rs = rsqrtf(sq * (1.f/CC) - m*m + EPSF);
#pragma unroll
        for (int c0 = 0; c0 < CC; c0 += 32) {
            int c = c0 + l;
            g_y2[(size_t)(base + r)*CC + c] =
                (as[r][c] - m) * rs * ln4_s[c] + ln4_b[c];
        }
    }
}

// =================== K4: softmax over j (per channel) + V aggregation ======
__global__ void __launch_bounds__(256) k4_softmax_agg()
{
    int ri = blockIdx.x;                 // b*N + i
    int b  = ri >> 7;
    int c  = threadIdx.x;
    const float* ap = g_attn + (size_t)ri * NN * CC + c;
    const float* vp = g_v    + (size_t)(b << 7) * CC + c;

    float m = -3.4e38f, s = 0.f, acc = 0.f;
#pragma unroll 4
    for (int j = 0; j < NN; j++) {
        float a    = ap[(size_t)j * CC];
        float nm   = fmaxf(m, a);
        float corr = __expf(m - nm);
        float p    = __expf(a - nm);
        s   = s   * corr + p;
        acc = acc * corr + p * vp[(size_t)j * CC];
        m = nm;
    }
    g_agg[ri*CC + c] = acc / s;
}

// =================== K5: node out proj + LN3 + node MLP + LN5 ==============
__global__ void __launch_bounds__(256) k5_node_mlp(
    const float* __restrict__ Won, const float* __restrict__ bon,
    const float* __restrict__ w1, const float* __restrict__ b1,
    const float* __restrict__ w2, const float* __restrict__ b2,
    const float* __restrict__ ln3_s, const float* __restrict__ ln3_b,
    const float* __restrict__ ln5_s, const float* __restrict__ ln5_b,
    float* __restrict__ xout)
{
    __shared__ __align__(16) float sagg[CC];
    __shared__ __align__(16) float sx2[CC];
    __shared__ __align__(16) float shid[HID];
    __shared__ float sred[8];
    int r = blockIdx.x, t = threadIdx.x;

    sagg[t] = g_agg[r*CC + t];
    __syncthreads();

    float no = bon[t];
    const float4* sa4 = (const float4*)sagg;
#pragma unroll 1
    for (int k4 = 0; k4 < CC/4; k4++) {
        float4 av = sa4[k4]; int kk = 4*k4;
        no = fmaf(av.x, Won[(kk+0)*CC+t], no);
        no = fmaf(av.y, Won[(kk+1)*CC+t], no);
        no = fmaf(av.z, Won[(kk+2)*CC+t], no);
        no = fmaf(av.w, Won[(kk+3)*CC+t], no);
    }
    float pre = g_x1[r*CC + t] + no;

    float mean = blockSum(pre, sred, t) * (1.f/CC);
    float d = pre - mean;
    float var = blockSum(d*d, sred, t) * (1.f/CC);
    float x2 = d * rsqrtf(var + EPSF) * ln3_s[t] + ln3_b[t];
    sx2[t] = x2;
    __syncthreads();

    const float4* sx24 = (const float4*)sx2;
#pragma unroll 1
    for (int hb = 0; hb < 4; hb++) {
        int h = hb*CC + t;
        float a = b1[h];
#pragma unroll 1
        for (int k4 = 0; k4 < CC/4; k4++) {
            float4 xv = sx24[k4]; int kk = 4*k4;
            a = fmaf(xv.x, w1[(kk+0)*HID+h], a);
            a = fmaf(xv.y, w1[(kk+1)*HID+h], a);
            a = fmaf(xv.z, w1[(kk+2)*HID+h], a);
            a = fmaf(xv.w, w1[(kk+3)*HID+h], a);
        }
        shid[h] = fmaxf(a, 0.f);
    }
    __syncthreads();

    float o = b2[t];
    const float4* sh4 = (const float4*)shid;
#pragma unroll 1
    for (int k4 = 0; k4 < HID/4; k4++) {
        float4 hv = sh4[k4]; int kk = 4*k4;
        o = fmaf(hv.x, w2[(kk+0)*CC+t], o);
        o = fmaf(hv.y, w2[(kk+1)*CC+t], o);
        o = fmaf(hv.z, w2[(kk+2)*CC+t], o);
        o = fmaf(hv.w, w2[(kk+3)*CC+t], o);
    }
    float pre2 = x2 + o;
    float mean2 = blockSum(pre2, sred, t) * (1.f/CC);
    float d2 = pre2 - mean2;
    float var2 = blockSum(d2*d2, sred, t) * (1.f/CC);
    xout[r*CC + t] = d2 * rsqrtf(var2 + EPSF) * ln5_s[t] + ln5_b[t];
}

// =================== K6: edge MLP (chunked through smem) + LN6 =============
__global__ void __launch_bounds__(256) k6_edge_mlp(
    const float* __restrict__ w1, const float* __restrict__ b1,
    const float* __restrict__ w2, const float* __restrict__ b2,
    const float* __restrict__ ln6_s, const float* __restrict__ ln6_b,
    float* __restrict__ yout)
{
    extern __shared__ float dsm[];
    float (*sy)[CC] = (float(*)[CC])dsm;               // 32 KB y2 tile
    float (*ss)[CC] = (float(*)[CC])(dsm + TILE*CC);   // 32 KB hid/out stage
    int base = blockIdx.x * TILE, t = threadIdx.x;

#pragma unroll
    for (int r = 0; r < TILE; r++)
        sy[r][t] = g_y2[(size_t)(base + r)*CC + t];

    float oacc[TILE];
#pragma unroll
    for (int r = 0; r < TILE; r++) oacc[r] = 0.f;
    __syncthreads();

#pragma unroll 1
    for (int ch = 0; ch < 4; ch++) {
        int h = ch*CC + t;                 // this thread's hidden column
        float hacc[TILE];
        float hb = b1[h];
#pragma unroll
        for (int r = 0; r < TILE; r++) hacc[r] = hb;

#pragma unroll 1
        for (int k4 = 0; k4 < CC/4; k4++) {
            int kk = 4*k4;
            float u0 = w1[(kk+0)*HID + h];
            float u1 = w1[(kk+1)*HID + h];
            float u2 = w1[(kk+2)*HID + h];
            float u3 = w1[(kk+3)*HID + h];
#pragma unroll
            for (int r = 0; r < TILE; r++) {
                float4 yv = ((const float4*)sy[r])[k4];
                hacc[r] = fmaf(yv.x, u0, hacc[r]);
                hacc[r] = fmaf(yv.y, u1, hacc[r]);
                hacc[r] = fmaf(yv.z, u2, hacc[r]);
                hacc[r] = fmaf(yv.w, u3, hacc[r]);
            }
        }
        __syncthreads();                   // ss free from previous chunk
#pragma unroll
        for (int r = 0; r < TILE; r++) ss[r][t] = fmaxf(hacc[r], 0.f);
        __syncthreads();

#pragma unroll 1
        for (int k4 = 0; k4 < CC/4; k4++) {
            int kk = ch*CC + 4*k4;
            float u0 = w2[(kk+0)*CC + t];
            float u1 = w2[(kk+1)*CC + t];
            float u2 = w2[(kk+2)*CC + t];
            float u3 = w2[(kk+3)*CC + t];
#pragma unroll
            for (int r = 0; r < TILE; r++) {
                float4 hv = ((const float4*)ss[r])[k4];
                oacc[r] = fmaf(hv.x, u0, oacc[r]);
                oacc[r] = fmaf(hv.y, u1, oacc[r]);
                oacc[r] = fmaf(hv.z, u2, oacc[r]);
                oacc[r] = fmaf(hv.w, u3, oacc[r]);
            }
        }
    }

    float b2v = b2[t];
    __syncthreads();
#pragma unroll
    for (int r = 0; r < TILE; r++)
        ss[r][t] = oacc[r] + b2v + sy[r][t];     // residual with y2
    __syncthreads();

    // LN6 per row, warp-per-row
    int w = t >> 5, l = t & 31;
#pragma unroll
    for (int u = 0; u < 4; u++) {
        int r = (u << 3) + w;
        float s = 0.f, sq = 0.f;
#pragma unroll
        for (int c0 = 0; c0 < CC; c0 += 32) {
            float v = ss[r][c0 + l];
            s += v; sq = fmaf(v, v, sq);
        }
        s = warpSum(s); sq = warpSum(sq);
        float m  = s * (1.f/CC);
        float rs = rsqrtf(sq * (1.f/CC) - m*m + EPSF);
#pragma unroll
        for (int c0 = 0; c0 < CC; c0 += 32) {
            int c = c0 + l;
            yout[(size_t)(base + r)*CC + c] =
                (ss[r][c] - m) * rs * ln6_s[c] + ln6_b[c];
        }
    }
}

// =================== launch ================================================
extern "C" void kernel_launch(void* const* d_in, const int* in_sizes, int n_in,
                              void* d_out, int out_size)
{
    const float* x   = (const float*)d_in[0];
    const float* y   = (const float*)d_in[1];
    const float* Wq  = (const float*)d_in[2];
    const float* bq  = (const float*)d_in[3];
    const float* Wk  = (const float*)d_in[4];
    const float* bk  = (const float*)d_in[5];
    const float* Wv  = (const float*)d_in[6];
    const float* bv  = (const float*)d_in[7];
    const float* We  = (const float*)d_in[8];
    const float* be  = (const float*)d_in[9];
    const float* Woe = (const float*)d_in[10];
    const float* boe = (const float*)d_in[11];
    const float* Won = (const float*)d_in[12];
    const float* bon = (const float*)d_in[13];
    const float* m1w1 = (const float*)d_in[14];
    const float* m1b1 = (const float*)d_in[15];
    const float* m1w2 = (const float*)d_in[16];
    const float* m1b2 = (const float*)d_in[17];
    const float* m2w1 = (const float*)d_in[18];
    const float* m2b1 = (const float*)d_in[19];
    const float* m2w2 = (const float*)d_in[20];
    const float* m2b2 = (const float*)d_in[21];
    const float* ln1s = (const float*)d_in[22];
    const float* ln1b = (const float*)d_in[23];
    const float* ln3s = (const float*)d_in[24];
    const float* ln3b = (const float*)d_in[25];
    const float* ln4s = (const float*)d_in[26];
    const float* ln4b = (const float*)d_in[27];
    const float* ln5s = (const float*)d_in[28];
    const float* ln5b = (const float*)d_in[29];
    const float* ln6s = (const float*)d_in[30];
    const float* ln6b = (const float*)d_in[31];

    float* xout = (float*)d_out;                   // (8,128,256)
    float* yout = (float*)d_out + ROWS*CC;         // (8,128,128,256)

    static int smem_set = 0;
    (void)smem_set;
    cudaFuncSetAttribute(k6_edge_mlp,
                         cudaFuncAttributeMaxDynamicSharedMemorySize,
                         2*TILE*CC*sizeof(float));

    k1_node_qkv<<<ROWS, 256>>>(x, Wq, bq, Wk, bk, Wv, bv, ln1s, ln1b);
    k2_edge_attn<<<EDGES/TILE, 256>>>(y, We, be);
    k3_edgeout_ln<<<EDGES/TILE, 256>>>(y, Woe, boe, ln4s, ln4b);
    k4_softmax_agg<<<ROWS, 256>>>();
    k5_node_mlp<<<ROWS, 256>>>(Won, bon, m1w1, m1b1, m1w2, m1b2,
                               ln3s, ln3b, ln5s, ln5b, xout);
    k6_edge_mlp<<<EDGES/TILE, 256, 2*TILE*CC*sizeof(float)>>>(
        m2w1, m2b1, m2w2, m2b2, ln6s, ln6b, yout);
}

// round 3
// speedup vs baseline: 1.0850x; 1.0850x over previous
#include <cuda_runtime.h>
#include <math.h>

#define BB   8
#define NN   128
#define CC   256
#define HID  1024
#define EPSF 1e-5f
#define TILE 32
#define ROWS (BB*NN)          /* 1024  */
#define EDGES (BB*NN*NN)      /* 131072 */
#define PITCH 36              /* floats: 144B rows, 16B aligned */

typedef unsigned long long ull;

// ---------------- scratch (device globals; no allocation anywhere) ---------
__device__ float g_x1[ROWS*CC];
__device__ float g_q [ROWS*CC];
__device__ float g_k [ROWS*CC];
__device__ float g_v [ROWS*CC];
__device__ float g_agg[ROWS*CC];
__device__ float g_attn[EDGES*CC];   // 134 MB
__device__ float g_y2 [EDGES*CC];    // 134 MB

// ---------------- packed f32x2 helpers -------------------------------------
#define FFMA2(c, a, b) \
    asm("fma.rn.f32x2 %0, %1, %2, %3;" : "=l"(c) : "l"(a), "l"(b), "l"(c))

__device__ __forceinline__ ull pack2(float a, float b) {
    ull r;
    asm("mov.b64 %0, {%1, %2};" : "=l"(r)
        : "r"(__float_as_uint(a)), "r"(__float_as_uint(b)));
    return r;
}
__device__ __forceinline__ void unpack2(ull p, float& a, float& b) {
    unsigned lo, hi;
    asm("mov.b64 {%0, %1}, %2;" : "=r"(lo), "=r"(hi) : "l"(p));
    a = __uint_as_float(lo); b = __uint_as_float(hi);
}

__device__ __forceinline__ float warpSum(float v) {
#pragma unroll
    for (int o = 16; o > 0; o >>= 1) v += __shfl_xor_sync(0xffffffffu, v, o);
    return v;
}

__device__ __forceinline__ float blockSum(float v, float* sred, int t) {
    v = warpSum(v);
    __syncthreads();
    if ((t & 31) == 0) sred[t >> 5] = v;
    __syncthreads();
    float tot = 0.f;
#pragma unroll
    for (int w = 0; w < 8; w++) tot += sred[w];
    return tot;
}

// =================== K1: LN1 + q,k,v projections (per node row) ============
__global__ void __launch_bounds__(256) k1_node_qkv(
    const float* __restrict__ x,
    const float* __restrict__ Wq, const float* __restrict__ bq,
    const float* __restrict__ Wk, const float* __restrict__ bk,
    const float* __restrict__ Wv, const float* __restrict__ bv,
    const float* __restrict__ ln1_s, const float* __restrict__ ln1_b)
{
    __shared__ __align__(16) float sx[CC];
    __shared__ float sred[8];
    int r = blockIdx.x, t = threadIdx.x;

    float xv = x[r*CC + t];
    float mean = blockSum(xv, sred, t) * (1.f/CC);
    float d = xv - mean;
    float var = blockSum(d*d, sred, t) * (1.f/CC);
    float rs = rsqrtf(var + EPSF);
    float x1 = d * rs * ln1_s[t] + ln1_b[t];
    sx[t] = x1;
    g_x1[r*CC + t] = x1;
    __syncthreads();

    float aq = bq[t], ak = bk[t], av = bv[t];
    const float4* sx4 = (const float4*)sx;
#pragma unroll 1
    for (int k4 = 0; k4 < CC/4; k4++) {
        float4 xv4 = sx4[k4];
        int kk = 4*k4;
        aq = fmaf(xv4.x, Wq[(kk+0)*CC+t], aq);
        aq = fmaf(xv4.y, Wq[(kk+1)*CC+t], aq);
        aq = fmaf(xv4.z, Wq[(kk+2)*CC+t], aq);
        aq = fmaf(xv4.w, Wq[(kk+3)*CC+t], aq);
        ak = fmaf(xv4.x, Wk[(kk+0)*CC+t], ak);
        ak = fmaf(xv4.y, Wk[(kk+1)*CC+t], ak);
        ak = fmaf(xv4.z, Wk[(kk+2)*CC+t], ak);
        ak = fmaf(xv4.w, Wk[(kk+3)*CC+t], ak);
        av = fmaf(xv4.x, Wv[(kk+0)*CC+t], av);
        av = fmaf(xv4.y, Wv[(kk+1)*CC+t], av);
        av = fmaf(xv4.z, Wv[(kk+2)*CC+t], av);
        av = fmaf(xv4.w, Wv[(kk+3)*CC+t], av);
    }
    g_q[r*CC+t] = aq;  g_k[r*CC+t] = ak;  g_v[r*CC+t] = av;
}

// =================== K2: e = y@We+be ; attn = (q*k/sqrt(dk))*(e+1)*e =======
// smem: sp[k][r] transposed tile (CC x PITCH floats = 36 KB, dynamic)
__global__ void __launch_bounds__(256) k2_edge_attn(
    const float* __restrict__ y,
    const float* __restrict__ We, const float* __restrict__ be)
{
    extern __shared__ __align__(16) float sp[];
    int base = blockIdx.x * TILE;
    int t = threadIdx.x;
    int ri = base / NN;
    int b  = ri >> 7;
    int j0 = base & (NN - 1);

#pragma unroll
    for (int r = 0; r < TILE; r++)
        sp[t*PITCH + r] = y[(size_t)(base + r)*CC + t];
    __syncthreads();

    ull acc[TILE/2];
    {
        float bev = be[t];
        ull bp = pack2(bev, bev);
#pragma unroll
        for (int i = 0; i < TILE/2; i++) acc[i] = bp;
    }

#pragma unroll 4
    for (int k = 0; k < CC; k++) {
        float w = We[k*CC + t];
        ull wp = pack2(w, w);
        const ulonglong2* row = (const ulonglong2*)(sp + k*PITCH);
#pragma unroll
        for (int q = 0; q < 8; q++) {
            ulonglong2 v = row[q];
            FFMA2(acc[2*q],   v.x, wp);
            FFMA2(acc[2*q+1], v.y, wp);
        }
    }

    float qv = g_q[ri*CC + t] * 0.17677669529663687f;  // 1/sqrt(32)
    int krow = (b << 7) + j0;
#pragma unroll
    for (int i = 0; i < TILE/2; i++) {
        float e0, e1;
        unpack2(acc[i], e0, e1);
        int r0 = 2*i, r1 = 2*i + 1;
        float kv0 = g_k[(krow + r0)*CC + t];
        float kv1 = g_k[(krow + r1)*CC + t];
        g_attn[(size_t)(base + r0)*CC + t] = qv * kv0 * (e0 + 1.f) * e0;
        g_attn[(size_t)(base + r1)*CC + t] = qv * kv1 * (e1 + 1.f) * e1;
    }
}

// =================== K3: edge_out = attn@Woe+boe ; y2 = LN4(edge_out + y) ==
#define LNP 257
__global__ void __launch_bounds__(256) k3_edgeout_ln(
    const float* __restrict__ y,
    const float* __restrict__ Woe, const float* __restrict__ boe,
    const float* __restrict__ ln4_s, const float* __restrict__ ln4_b)
{
    extern __shared__ __align__(16) float sp[];
    int base = blockIdx.x * TILE;
    int t = threadIdx.x;

#pragma unroll
    for (int r = 0; r < TILE; r++)
        sp[t*PITCH + r] = g_attn[(size_t)(base + r)*CC + t];
    __syncthreads();

    ull acc[TILE/2];
    {
        float bv = boe[t];
        ull bp = pack2(bv, bv);
#pragma unroll
        for (int i = 0; i < TILE/2; i++) acc[i] = bp;
    }

#pragma unroll 4
    for (int k = 0; k < CC; k++) {
        float w = Woe[k*CC + t];
        ull wp = pack2(w, w);
        const ulonglong2* row = (const ulonglong2*)(sp + k*PITCH);
#pragma unroll
        for (int q = 0; q < 8; q++) {
            ulonglong2 v = row[q];
            FFMA2(acc[2*q],   v.x, wp);
            FFMA2(acc[2*q+1], v.y, wp);
        }
    }
    __syncthreads();                 // done reading sp; reuse as LN buffer

    float* ln = sp;                  // [TILE][LNP]
#pragma unroll
    for (int i = 0; i < TILE/2; i++) {
        float e0, e1;
        unpack2(acc[i], e0, e1);
        int r0 = 2*i, r1 = 2*i + 1;
        ln[r0*LNP + t] = e0 + y[(size_t)(base + r0)*CC + t];
        ln[r1*LNP + t] = e1 + y[(size_t)(base + r1)*CC + t];
    }
    __syncthreads();

    int w = t >> 5, l = t & 31;
#pragma unroll
    for (int u = 0; u < 4; u++) {
        int r = (u << 3) + w;
        float s = 0.f, sq = 0.f;
#pragma unroll
        for (int c0 = 0; c0 < CC; c0 += 32) {
            float v = ln[r*LNP + c0 + l];
            s += v; sq = fmaf(v, v, sq);
        }
        s = warpSum(s); sq = warpSum(sq);
        float m  = s * (1.f/CC);
        float rs = rsqrtf(sq * (1.f/CC) - m*m + EPSF);
#pragma unroll
        for (int c0 = 0; c0 < CC; c0 += 32) {
            int c = c0 + l;
            g_y2[(size_t)(base + r)*CC + c] =
                (ln[r*LNP + c] - m) * rs * ln4_s[c] + ln4_b[c];
        }
    }
}

// =================== K4: softmax over j (per channel) + V aggregation ======
__global__ void __launch_bounds__(256) k4_softmax_agg()
{
    int ri = blockIdx.x;
    int b  = ri >> 7;
    int c  = threadIdx.x;
    const float* ap = g_attn + (size_t)ri * NN * CC + c;
    const float* vp = g_v    + (size_t)(b << 7) * CC + c;

    float m = -3.4e38f, s = 0.f, acc = 0.f;
#pragma unroll 4
    for (int j = 0; j < NN; j++) {
        float a    = ap[(size_t)j * CC];
        float nm   = fmaxf(m, a);
        float corr = __expf(m - nm);
        float p    = __expf(a - nm);
        s   = s   * corr + p;
        acc = acc * corr + p * vp[(size_t)j * CC];
        m = nm;
    }
    g_agg[ri*CC + c] = acc / s;
}

// =================== K5: node out proj + LN3 + node MLP + LN5 ==============
__global__ void __launch_bounds__(256) k5_node_mlp(
    const float* __restrict__ Won, const float* __restrict__ bon,
    const float* __restrict__ w1, const float* __restrict__ b1,
    const float* __restrict__ w2, const float* __restrict__ b2,
    const float* __restrict__ ln3_s, const float* __restrict__ ln3_b,
    const float* __restrict__ ln5_s, const float* __restrict__ ln5_b,
    float* __restrict__ xout)
{
    __shared__ __align__(16) float sagg[CC];
    __shared__ __align__(16) float sx2[CC];
    __shared__ __align__(16) float shid[HID];
    __shared__ float sred[8];
    int r = blockIdx.x, t = threadIdx.x;

    sagg[t] = g_agg[r*CC + t];
    __syncthreads();

    float no = bon[t];
    const float4* sa4 = (const float4*)sagg;
#pragma unroll 1
    for (int k4 = 0; k4 < CC/4; k4++) {
        float4 av = sa4[k4]; int kk = 4*k4;
        no = fmaf(av.x, Won[(kk+0)*CC+t], no);
        no = fmaf(av.y, Won[(kk+1)*CC+t], no);
        no = fmaf(av.z, Won[(kk+2)*CC+t], no);
        no = fmaf(av.w, Won[(kk+3)*CC+t], no);
    }
    float pre = g_x1[r*CC + t] + no;

    float mean = blockSum(pre, sred, t) * (1.f/CC);
    float d = pre - mean;
    float var = blockSum(d*d, sred, t) * (1.f/CC);
    float x2 = d * rsqrtf(var + EPSF) * ln3_s[t] + ln3_b[t];
    sx2[t] = x2;
    __syncthreads();

    const float4* sx24 = (const float4*)sx2;
#pragma unroll 1
    for (int hb = 0; hb < 4; hb++) {
        int h = hb*CC + t;
        float a = b1[h];
#pragma unroll 1
        for (int k4 = 0; k4 < CC/4; k4++) {
            float4 xv = sx24[k4]; int kk = 4*k4;
            a = fmaf(xv.x, w1[(kk+0)*HID+h], a);
            a = fmaf(xv.y, w1[(kk+1)*HID+h], a);
            a = fmaf(xv.z, w1[(kk+2)*HID+h], a);
            a = fmaf(xv.w, w1[(kk+3)*HID+h], a);
        }
        shid[h] = fmaxf(a, 0.f);
    }
    __syncthreads();

    float o = b2[t];
    const float4* sh4 = (const float4*)shid;
#pragma unroll 1
    for (int k4 = 0; k4 < HID/4; k4++) {
        float4 hv = sh4[k4]; int kk = 4*k4;
        o = fmaf(hv.x, w2[(kk+0)*CC+t], o);
        o = fmaf(hv.y, w2[(kk+1)*CC+t], o);
        o = fmaf(hv.z, w2[(kk+2)*CC+t], o);
        o = fmaf(hv.w, w2[(kk+3)*CC+t], o);
    }
    float pre2 = x2 + o;
    float mean2 = blockSum(pre2, sred, t) * (1.f/CC);
    float d2 = pre2 - mean2;
    float var2 = blockSum(d2*d2, sred, t) * (1.f/CC);
    xout[r*CC + t] = d2 * rsqrtf(var2 + EPSF) * ln5_s[t] + ln5_b[t];
}

// =================== K6: edge MLP + LN6 (f32x2, transposed staging) ========
// dynamic smem: sy = [CC][PITCH] (36 KB), sh = [CC][PITCH] (36 KB)
__global__ void __launch_bounds__(256) k6_edge_mlp(
    const float* __restrict__ w1, const float* __restrict__ b1,
    const float* __restrict__ w2, const float* __restrict__ b2,
    const float* __restrict__ ln6_s, const float* __restrict__ ln6_b,
    float* __restrict__ yout)
{
    extern __shared__ __align__(16) float dsm[];
    float* sy = dsm;                  // CC*PITCH floats
    float* sh = dsm + CC*PITCH;       // CC*PITCH floats
    int base = blockIdx.x * TILE, t = threadIdx.x;

#pragma unroll
    for (int r = 0; r < TILE; r++)
        sy[t*PITCH + r] = g_y2[(size_t)(base + r)*CC + t];

    ull oacc[TILE/2];
#pragma unroll
    for (int i = 0; i < TILE/2; i++) oacc[i] = 0ull;
    __syncthreads();

#pragma unroll 1
    for (int ch = 0; ch < 4; ch++) {
        int h = ch*CC + t;
        ull hacc[TILE/2];
        {
            float hb = b1[h];
            ull hp = pack2(hb, hb);
#pragma unroll
            for (int i = 0; i < TILE/2; i++) hacc[i] = hp;
        }

#pragma unroll 4
        for (int k = 0; k < CC; k++) {
            float w = w1[k*HID + h];
            ull wp = pack2(w, w);
            const ulonglong2* row = (const ulonglong2*)(sy + k*PITCH);
#pragma unroll
            for (int q = 0; q < 8; q++) {
                ulonglong2 v = row[q];
                FFMA2(hacc[2*q],   v.x, wp);
                FFMA2(hacc[2*q+1], v.y, wp);
            }
        }
        __syncthreads();              // prior chunk's sh reads done
#pragma unroll
        for (int i = 0; i < TILE/2; i++) {
            float e0, e1;
            unpack2(hacc[i], e0, e1);
            sh[t*PITCH + 2*i]     = fmaxf(e0, 0.f);
            sh[t*PITCH + 2*i + 1] = fmaxf(e1, 0.f);
        }
        __syncthreads();

#pragma unroll 4
        for (int k = 0; k < CC; k++) {
            float w = w2[(ch*CC + k)*CC + t];
            ull wp = pack2(w, w);
            const ulonglong2* row = (const ulonglong2*)(sh + k*PITCH);
#pragma unroll
            for (int q = 0; q < 8; q++) {
                ulonglong2 v = row[q];
                FFMA2(oacc[2*q],   v.x, wp);
                FFMA2(oacc[2*q+1], v.y, wp);
            }
        }
    }

    __syncthreads();                  // sh free; reuse as LN buffer
    float* ln = sh;                   // [TILE][LNP]
    {
        float b2v = b2[t];
#pragma unroll
        for (int i = 0; i < TILE/2; i++) {
            float e0, e1;
            unpack2(oacc[i], e0, e1);
            int r0 = 2*i, r1 = 2*i + 1;
            ln[r0*LNP + t] = e0 + b2v + sy[t*PITCH + r0];
            ln[r1*LNP + t] = e1 + b2v + sy[t*PITCH + r1];
        }
    }
    __syncthreads();

    int w = t >> 5, l = t & 31;
#pragma unroll
    for (int u = 0; u < 4; u++) {
        int r = (u << 3) + w;
        float s = 0.f, sq = 0.f;
#pragma unroll
        for (int c0 = 0; c0 < CC; c0 += 32) {
            float v = ln[r*LNP + c0 + l];
            s += v; sq = fmaf(v, v, sq);
        }
        s = warpSum(s); sq = warpSum(sq);
        float m  = s * (1.f/CC);
        float rs = rsqrtf(sq * (1.f/CC) - m*m + EPSF);
#pragma unroll
        for (int c0 = 0; c0 < CC; c0 += 32) {
            int c = c0 + l;
            yout[(size_t)(base + r)*CC + c] =
                (ln[r*LNP + c] - m) * rs * ln6_s[c] + ln6_b[c];
        }
    }
}

// =================== launch ================================================
extern "C" void kernel_launch(void* const* d_in, const int* in_sizes, int n_in,
                              void* d_out, int out_size)
{
    const float* x   = (const float*)d_in[0];
    const float* y   = (const float*)d_in[1];
    const float* Wq  = (const float*)d_in[2];
    const float* bq  = (const float*)d_in[3];
    const float* Wk  = (const float*)d_in[4];
    const float* bk  = (const float*)d_in[5];
    const float* Wv  = (const float*)d_in[6];
    const float* bv  = (const float*)d_in[7];
    const float* We  = (const float*)d_in[8];
    const float* be  = (const float*)d_in[9];
    const float* Woe = (const float*)d_in[10];
    const float* boe = (const float*)d_in[11];
    const float* Won = (const float*)d_in[12];
    const float* bon = (const float*)d_in[13];
    const float* m1w1 = (const float*)d_in[14];
    const float* m1b1 = (const float*)d_in[15];
    const float* m1w2 = (const float*)d_in[16];
    const float* m1b2 = (const float*)d_in[17];
    const float* m2w1 = (const float*)d_in[18];
    const float* m2b1 = (const float*)d_in[19];
    const float* m2w2 = (const float*)d_in[20];
    const float* m2b2 = (const float*)d_in[21];
    const float* ln1s = (const float*)d_in[22];
    const float* ln1b = (const float*)d_in[23];
    const float* ln3s = (const float*)d_in[24];
    const float* ln3b = (const float*)d_in[25];
    const float* ln4s = (const float*)d_in[26];
    const float* ln4b = (const float*)d_in[27];
    const float* ln5s = (const float*)d_in[28];
    const float* ln5b = (const float*)d_in[29];
    const float* ln6s = (const float*)d_in[30];
    const float* ln6b = (const float*)d_in[31];

    float* xout = (float*)d_out;                   // (8,128,256)
    float* yout = (float*)d_out + ROWS*CC;         // (8,128,128,256)

    const int smem1 = CC*PITCH*sizeof(float);      // 36 KB
    const int smem2 = 2*CC*PITCH*sizeof(float);    // 72 KB
    cudaFuncSetAttribute(k2_edge_attn,
                         cudaFuncAttributeMaxDynamicSharedMemorySize, smem1);
    cudaFuncSetAttribute(k3_edgeout_ln,
                         cudaFuncAttributeMaxDynamicSharedMemorySize, smem1);
    cudaFuncSetAttribute(k6_edge_mlp,
                         cudaFuncAttributeMaxDynamicSharedMemorySize, smem2);

    k1_node_qkv<<<ROWS, 256>>>(x, Wq, bq, Wk, bk, Wv, bv, ln1s, ln1b);
    k2_edge_attn<<<EDGES/TILE, 256, smem1>>>(y, We, be);
    k3_edgeout_ln<<<EDGES/TILE, 256, smem1>>>(y, Woe, boe, ln4s, ln4b);
    k4_softmax_agg<<<ROWS, 256>>>();
    k5_node_mlp<<<ROWS, 256>>>(Won, bon, m1w1, m1b1, m1w2, m1b2,
                               ln3s, ln3b, ln5s, ln5b, xout);
    k6_edge_mlp<<<EDGES/TILE, 256, smem2>>>(
        m2w1, m2b1, m2w2, m2b2, ln6s, ln6b, yout);
}